// round 3
// baseline (speedup 1.0000x reference)
#include <cuda_runtime.h>
#include <math.h>

// ---------------------------------------------------------------------------
// AttentionLSTM (show-attend-tell) forward, B=32 T=128 P=196 ENC=2048
// DEC=ATT=EMB=512 V=10000.  All fp32; inner products use packed fma.rn.f32x2.
// ---------------------------------------------------------------------------

#define B_   32
#define T_   128
#define P_   196
#define ENC_ 2048
#define DEC_ 512
#define ATT_ 512
#define EMB_ 512
#define V_   10000
#define XK_  3072          // (EMB+ENC) + DEC  = 2560 + 512

typedef unsigned long long u64;

__device__ __forceinline__ u64 ld2u(const float* p) {
    return *reinterpret_cast<const u64*>(p);     // callers guarantee 8B alignment
}
__device__ __forceinline__ void fma2(u64& c, u64 a, u64 b) {
    asm("fma.rn.f32x2 %0, %1, %2, %0;" : "+l"(c) : "l"(a), "l"(b));
}
__device__ __forceinline__ float fold2(u64 v) {
    return __uint_as_float((unsigned)v) + __uint_as_float((unsigned)(v >> 32));
}
__device__ __forceinline__ float sigf(float x) { return 1.0f / (1.0f + expf(-x)); }

// ----------------------------- device scratch ------------------------------
__device__ float g_att1[B_ * P_ * ATT_];     // 12.8 MB
__device__ float g_mean[B_ * ENC_];
__device__ float g_hbuf[2][B_ * DEC_];
__device__ float g_cbuf[2][B_ * DEC_];
__device__ float g_hnew[B_ * DEC_];
__device__ float g_att2[B_ * ATT_];
__device__ float g_gate[B_ * ENC_];
__device__ float g_xawe[B_ * ENC_];
__device__ float g_alpha[B_ * P_];

// ----------------------------- k_mean --------------------------------------
// mean over the 196 positions.  grid 256 x 256 threads.
__global__ void k_mean(const float* __restrict__ bimgs) {
    int idx = blockIdx.x * 256 + threadIdx.x;          // 0 .. 65535
    int b = idx >> 11, e = idx & 2047;
    const float* p = bimgs + (size_t)b * P_ * ENC_ + e;
    float s = 0.f;
#pragma unroll 4
    for (int pp = 0; pp < P_; ++pp) s += p[(size_t)pp * ENC_];
    g_mean[b * ENC_ + e] = s * (1.0f / 196.0f);
}

// ----------------------------- k_att1 --------------------------------------
// att1[bp, a] = imgs[bp, :] . enc_att_W[a, :] + b     (6272 x 512, K = 2048)
// 64x64 tile, BK=16, 256 threads, 4x4 micro-tile, f32x2 packed over k-pairs.
__global__ void k_att1(const float* __restrict__ bimgs,
                       const float* __restrict__ Wq,
                       const float* __restrict__ bq) {
    __shared__ __align__(16) float As[64][18];
    __shared__ __align__(16) float Bs[64][18];
    int tid = threadIdx.x;
    int r0 = blockIdx.x * 64;
    int c0 = blockIdx.y * 64;
    int tx = tid & 15, ty = tid >> 4;
    u64 acc[4][4];
#pragma unroll
    for (int i = 0; i < 4; i++)
#pragma unroll
        for (int j = 0; j < 4; j++) acc[i][j] = 0ull;

    for (int k0 = 0; k0 < ENC_; k0 += 16) {
#pragma unroll
        for (int i = 0; i < 4; i++) {
            int flat = i * 256 + tid;
            int r = flat >> 4, k = flat & 15;
            As[r][k] = bimgs[(size_t)(r0 + r) * ENC_ + k0 + k];
            Bs[r][k] = Wq[(size_t)(c0 + r) * ENC_ + k0 + k];
        }
        __syncthreads();
#pragma unroll
        for (int kp = 0; kp < 8; kp++) {
            u64 a[4], b[4];
#pragma unroll
            for (int i = 0; i < 4; i++) a[i] = ld2u(&As[ty + 16 * i][2 * kp]);
#pragma unroll
            for (int j = 0; j < 4; j++) b[j] = ld2u(&Bs[tx + 16 * j][2 * kp]);
#pragma unroll
            for (int i = 0; i < 4; i++)
#pragma unroll
                for (int j = 0; j < 4; j++) fma2(acc[i][j], a[i], b[j]);
        }
        __syncthreads();
    }
#pragma unroll
    for (int i = 0; i < 4; i++)
#pragma unroll
        for (int j = 0; j < 4; j++) {
            int R = r0 + ty + 16 * i, C = c0 + tx + 16 * j;
            g_att1[(size_t)R * ATT_ + C] = fold2(acc[i][j]) + bq[C];
        }
}

// ----------------------------- k_init_hc -----------------------------------
// h0 | c0 = mean @ {init_h_W, init_c_W}^T + bias.   M=32, N=1024, K=2048.
__global__ void k_init_hc(const float* __restrict__ Wh, const float* __restrict__ bh,
                          const float* __restrict__ Wc, const float* __restrict__ bc) {
    __shared__ __align__(16) float xs[32][66];
    __shared__ __align__(16) float ws[16][66];
    int tid = threadIdx.x, lane = tid & 31, w = tid >> 5;
    int j0 = blockIdx.x * 16;
    int c0 = 2 * w, c1 = c0 + 1;
    u64 acc0 = 0ull, acc1 = 0ull;

    for (int k0 = 0; k0 < ENC_; k0 += 64) {
#pragma unroll
        for (int i = 0; i < 8; i++) {
            int flat = i * 256 + tid; int m = flat >> 6, k = flat & 63;
            xs[m][k] = g_mean[m * ENC_ + k0 + k];
        }
#pragma unroll
        for (int i = 0; i < 4; i++) {
            int flat = i * 256 + tid; int c = flat >> 6, k = flat & 63;
            int j = j0 + c;
            ws[c][k] = (j < DEC_) ? Wh[(size_t)j * ENC_ + k0 + k]
                                  : Wc[(size_t)(j - DEC_) * ENC_ + k0 + k];
        }
        __syncthreads();
#pragma unroll 8
        for (int kp = 0; kp < 32; kp++) {
            u64 a = ld2u(&xs[lane][2 * kp]);
            fma2(acc0, a, ld2u(&ws[c0][2 * kp]));
            fma2(acc1, a, ld2u(&ws[c1][2 * kp]));
        }
        __syncthreads();
    }
    int j;
    j = j0 + c0;
    if (j < DEC_) g_hbuf[0][lane * DEC_ + j] = fold2(acc0) + bh[j];
    else          g_cbuf[0][lane * DEC_ + (j - DEC_)] = fold2(acc0) + bc[j - DEC_];
    j = j0 + c1;
    if (j < DEC_) g_hbuf[0][lane * DEC_ + j] = fold2(acc1) + bh[j];
    else          g_cbuf[0][lane * DEC_ + (j - DEC_)] = fold2(acc1) + bc[j - DEC_];
}

// ----------------------------- k_escore ------------------------------------
// e[p] = relu(att1[b,p,:] + att2[b,:]) . w + b ; softmax over p ; emit alpha.
__global__ void k_escore(const float* __restrict__ full_att_W,
                         const float* __restrict__ full_att_b,
                         const int*   __restrict__ bxlen,
                         float* __restrict__ out_alpha, int t) {
    __shared__ float att2_s[ATT_];
    __shared__ float w_s[ATT_];
    __shared__ float e_s[P_];
    __shared__ float red[256];
    int b = blockIdx.x, tid = threadIdx.x;
    for (int i = tid; i < ATT_; i += 256) {
        att2_s[i] = g_att2[b * ATT_ + i];
        w_s[i] = full_att_W[i];
    }
    __syncthreads();
    int warp = tid >> 5, lane = tid & 31;
    float fb = full_att_b[0];
    for (int p = warp; p < P_; p += 8) {
        const float* row = g_att1 + ((size_t)b * P_ + p) * ATT_;
        float s = 0.f;
#pragma unroll 4
        for (int a = lane; a < ATT_; a += 32) {
            float v = fmaxf(row[a] + att2_s[a], 0.f);
            s = fmaf(v, w_s[a], s);
        }
#pragma unroll
        for (int o = 16; o; o >>= 1) s += __shfl_xor_sync(0xffffffffu, s, o);
        if (!lane) e_s[p] = s + fb;
    }
    __syncthreads();
    float v = (tid < P_) ? e_s[tid] : -1e30f;
    red[tid] = v; __syncthreads();
    for (int o = 128; o; o >>= 1) { if (tid < o) red[tid] = fmaxf(red[tid], red[tid + o]); __syncthreads(); }
    float mx = red[0]; __syncthreads();
    float ex = (tid < P_) ? expf(v - mx) : 0.f;
    red[tid] = ex; __syncthreads();
    for (int o = 128; o; o >>= 1) { if (tid < o) red[tid] += red[tid + o]; __syncthreads(); }
    float inv = 1.0f / red[0];
    if (tid < P_) {
        float alpha = ex * inv;
        g_alpha[b * P_ + tid] = alpha;
        bool act = (t < bxlen[b]);
        out_alpha[((size_t)b * T_ + t) * P_ + tid] = act ? alpha : 0.f;
    }
}

// ----------------------------- k_awe ---------------------------------------
// xawe[b,e] = gate[b,e] * sum_p alpha[b,p] * imgs[b,p,e]
__global__ void k_awe(const float* __restrict__ bimgs) {
    __shared__ float al[P_];
    int b = blockIdx.x, tid = threadIdx.x;
    if (tid < P_) al[tid] = g_alpha[b * P_ + tid];
    __syncthreads();
    int e = blockIdx.y * 256 + tid;
    const float* base = bimgs + (size_t)b * P_ * ENC_ + e;
    float s = 0.f;
#pragma unroll 4
    for (int p = 0; p < P_; ++p) s = fmaf(al[p], base[(size_t)p * ENC_], s);
    g_xawe[b * ENC_ + e] = g_gate[b * ENC_ + e] * s;
}

// ----------------------------- k_cell --------------------------------------
// gates = [emb_t, xawe] @ W_ih^T + h @ W_hh^T + biases ; fused LSTM update.
// Block handles 4 cell indices x 4 gate groups (16 cols).  grid = 128.
__global__ void k_cell(const float* __restrict__ emb_W, const int* __restrict__ bx,
                       const float* __restrict__ W_ih, const float* __restrict__ b_ih,
                       const float* __restrict__ W_hh, const float* __restrict__ b_hh,
                       const int* __restrict__ bxlen, int t, int par) {
    __shared__ __align__(16) float xs[32][66];
    __shared__ __align__(16) float ws[16][66];
    __shared__ float res[16][33];
    __shared__ int idx_s[32];
    int tid = threadIdx.x, lane = tid & 31, w = tid >> 5;
    if (tid < 32) idx_s[tid] = bx[tid * T_ + t];
    __syncthreads();
    int j0 = blockIdx.x * 4;
    int c0 = 2 * w, c1 = c0 + 1;
    int jc0 = ((c0 >> 2) << 9) + j0 + (c0 & 3);
    int jc1 = ((c1 >> 2) << 9) + j0 + (c1 & 3);
    const float* hin = g_hbuf[par];
    u64 acc0 = 0ull, acc1 = 0ull;

    for (int k0 = 0; k0 < XK_; k0 += 64) {
#pragma unroll
        for (int i = 0; i < 8; i++) {
            int flat = i * 256 + tid; int m = flat >> 6, k = flat & 63;
            int kk = k0 + k;
            float v;
            if (kk < EMB_)            v = emb_W[(size_t)idx_s[m] * EMB_ + kk];
            else if (kk < EMB_ + ENC_) v = g_xawe[m * ENC_ + (kk - EMB_)];
            else                       v = hin[m * DEC_ + (kk - EMB_ - ENC_)];
            xs[m][k] = v;
        }
#pragma unroll
        for (int i = 0; i < 4; i++) {
            int flat = i * 256 + tid; int c = flat >> 6, k = flat & 63;
            int kk = k0 + k;
            int j = ((c >> 2) << 9) + j0 + (c & 3);
            ws[c][k] = (kk < EMB_ + ENC_) ? W_ih[(size_t)j * (EMB_ + ENC_) + kk]
                                          : W_hh[(size_t)j * DEC_ + (kk - EMB_ - ENC_)];
        }
        __syncthreads();
#pragma unroll 8
        for (int kp = 0; kp < 32; kp++) {
            u64 a = ld2u(&xs[lane][2 * kp]);
            fma2(acc0, a, ld2u(&ws[c0][2 * kp]));
            fma2(acc1, a, ld2u(&ws[c1][2 * kp]));
        }
        __syncthreads();
    }
    res[c0][lane] = fold2(acc0) + b_ih[jc0] + b_hh[jc0];
    res[c1][lane] = fold2(acc1) + b_ih[jc1] + b_hh[jc1];
    __syncthreads();
    if (tid < 128) {
        int m = tid & 31, ci = tid >> 5;
        int j = j0 + ci;
        float i_ = sigf(res[ci][m]);
        float f_ = sigf(res[4 + ci][m]);
        float gg = tanhf(res[8 + ci][m]);
        float o_ = sigf(res[12 + ci][m]);
        float h_old = g_hbuf[par][m * DEC_ + j];
        float c_old = g_cbuf[par][m * DEC_ + j];
        float cn = f_ * c_old + i_ * gg;
        float hn = o_ * tanhf(cn);
        g_hnew[m * DEC_ + j] = hn;
        bool act = (t < bxlen[m]);
        g_hbuf[par ^ 1][m * DEC_ + j] = act ? hn : h_old;
        g_cbuf[par ^ 1][m * DEC_ + j] = act ? cn : c_old;
    }
}

// ----------------------------- k_proj --------------------------------------
// seg0: preds = hnew @ fc_W^T + fc_b  (masked store to out)   [625 blocks]
// seg1: att2  = h2 @ dec_att_W^T + b                          [32 blocks]
// seg2: gate  = sigmoid(h2 @ f_beta_W^T + b)                  [128 blocks]
__global__ void k_proj(const float* __restrict__ fc_W, const float* __restrict__ fc_b,
                       const float* __restrict__ dec_att_W, const float* __restrict__ dec_att_b,
                       const float* __restrict__ f_beta_W, const float* __restrict__ f_beta_b,
                       const int* __restrict__ bxlen, float* __restrict__ out_pred,
                       int t, int ip, int parnext) {
    __shared__ __align__(16) float xs[32][66];
    __shared__ __align__(16) float ws[16][66];
    int tid = threadIdx.x, lane = tid & 31, w = tid >> 5;
    int pb = ip ? (V_ / 16) : 0;
    int bi = blockIdx.x;
    int seg, j0;
    const float* W; const float* X;
    if (bi < pb)            { seg = 0; j0 = bi * 16;            W = fc_W;      X = g_hnew; }
    else if (bi < pb + 32)  { seg = 1; j0 = (bi - pb) * 16;      W = dec_att_W; X = g_hbuf[parnext]; }
    else                    { seg = 2; j0 = (bi - pb - 32) * 16; W = f_beta_W;  X = g_hbuf[parnext]; }
    int c0 = 2 * w, c1 = c0 + 1;
    u64 acc0 = 0ull, acc1 = 0ull;

    for (int k0 = 0; k0 < DEC_; k0 += 64) {
#pragma unroll
        for (int i = 0; i < 8; i++) {
            int flat = i * 256 + tid; int m = flat >> 6, k = flat & 63;
            xs[m][k] = X[m * DEC_ + k0 + k];
        }
#pragma unroll
        for (int i = 0; i < 4; i++) {
            int flat = i * 256 + tid; int c = flat >> 6, k = flat & 63;
            ws[c][k] = W[(size_t)(j0 + c) * DEC_ + k0 + k];
        }
        __syncthreads();
#pragma unroll 8
        for (int kp = 0; kp < 32; kp++) {
            u64 a = ld2u(&xs[lane][2 * kp]);
            fma2(acc0, a, ld2u(&ws[c0][2 * kp]));
            fma2(acc1, a, ld2u(&ws[c1][2 * kp]));
        }
        __syncthreads();
    }
#pragma unroll
    for (int cc = 0; cc < 2; cc++) {
        int j = j0 + (cc ? c1 : c0);
        float v = fold2(cc ? acc1 : acc0);
        int m = lane;
        if (seg == 0) {
            v += fc_b[j];
            bool act = (t < bxlen[m]);
            out_pred[((size_t)m * T_ + t) * V_ + j] = act ? v : 0.f;
        } else if (seg == 1) {
            g_att2[m * ATT_ + j] = v + dec_att_b[j];
        } else {
            g_gate[m * ENC_ + j] = sigf(v + f_beta_b[j]);
        }
    }
}

// ----------------------------- launch --------------------------------------
extern "C" void kernel_launch(void* const* d_in, const int* in_sizes, int n_in,
                              void* d_out, int out_size) {
    (void)in_sizes; (void)n_in; (void)out_size;
    const float* bimgs      = (const float*)d_in[0];
    const int*   bx         = (const int*)  d_in[1];
    const int*   bxlen      = (const int*)  d_in[2];
    const float* emb_W      = (const float*)d_in[3];
    const float* enc_att_W  = (const float*)d_in[4];
    const float* enc_att_b  = (const float*)d_in[5];
    const float* dec_att_W  = (const float*)d_in[6];
    const float* dec_att_b  = (const float*)d_in[7];
    const float* full_att_W = (const float*)d_in[8];
    const float* full_att_b = (const float*)d_in[9];
    const float* init_h_W   = (const float*)d_in[10];
    const float* init_h_b   = (const float*)d_in[11];
    const float* init_c_W   = (const float*)d_in[12];
    const float* init_c_b   = (const float*)d_in[13];
    const float* f_beta_W   = (const float*)d_in[14];
    const float* f_beta_b   = (const float*)d_in[15];
    const float* W_ih       = (const float*)d_in[16];
    const float* b_ih       = (const float*)d_in[17];
    const float* W_hh       = (const float*)d_in[18];
    const float* b_hh       = (const float*)d_in[19];
    const float* fc_W       = (const float*)d_in[20];
    const float* fc_b       = (const float*)d_in[21];

    float* out_pred  = (float*)d_out;
    float* out_alpha = out_pred + (size_t)B_ * T_ * V_;

    k_mean   <<<256, 256>>>(bimgs);
    k_att1   <<<dim3(98, 8), 256>>>(bimgs, enc_att_W, enc_att_b);
    k_init_hc<<<64, 256>>>(init_h_W, init_h_b, init_c_W, init_c_b);
    // initial att2/gate from h0 (no preds segment)
    k_proj<<<160, 256>>>(fc_W, fc_b, dec_att_W, dec_att_b, f_beta_W, f_beta_b,
                         bxlen, out_pred, 0, 0, 0);

    for (int t = 0; t < T_; ++t) {
        int par = t & 1;
        k_escore<<<32, 256>>>(full_att_W, full_att_b, bxlen, out_alpha, t);
        k_awe   <<<dim3(32, 8), 256>>>(bimgs);
        k_cell  <<<128, 256>>>(emb_W, bx, W_ih, b_ih, W_hh, b_hh, bxlen, t, par);
        k_proj  <<<625 + 32 + 128, 256>>>(fc_W, fc_b, dec_att_W, dec_att_b,
                                          f_beta_W, f_beta_b, bxlen, out_pred,
                                          t, 1, par ^ 1);
    }
}

// round 6
// speedup vs baseline: 2.5179x; 2.5179x over previous
#include <cuda_runtime.h>
#include <math.h>

// ---------------------------------------------------------------------------
// AttentionLSTM forward, B=32 T=128 P=196 ENC=2048 DEC=ATT=EMB=512 V=10000.
// All fp32; inner products use packed fma.rn.f32x2.
// Unified 32xN GEMM engine, compile-time specialized per mode (template) to
// keep each instantiation small and branch-free in the hot loop.
// ---------------------------------------------------------------------------

#define B_   32
#define T_   128
#define P_   196
#define ENC_ 2048
#define DEC_ 512
#define ATT_ 512
#define EMB_ 512
#define V_   10000
#define XK_  3072
#define NCH_ 12
#define KCH_ (XK_ / NCH_)     // 256

typedef unsigned long long u64;

__device__ __forceinline__ void fma2(u64& c, u64 a, u64 b) {
    asm("fma.rn.f32x2 %0, %1, %2, %0;" : "+l"(c) : "l"(a), "l"(b));
}
__device__ __forceinline__ float fold2(u64 v) {
    return __uint_as_float((unsigned)v) + __uint_as_float((unsigned)(v >> 32));
}
__device__ __forceinline__ float sigf(float x) { return 1.0f / (1.0f + expf(-x)); }

// ----------------------------- device scratch ------------------------------
__device__ float g_att1[B_ * P_ * ATT_];         // 12.8 MB
__device__ float g_mean[B_ * ENC_];
__device__ float g_hbuf[2][B_ * DEC_];
__device__ float g_cbuf[2][B_ * DEC_];
__device__ float g_hnew[B_ * DEC_];
__device__ float g_att2[B_ * ATT_];
__device__ float g_gate[B_ * ENC_];
__device__ float g_xawe[B_ * ENC_];
__device__ float g_alpha[B_ * P_];
__device__ float g_cpart[NCH_ * B_ * 2048];      // 3 MB LSTM gate partials

// ----------------------------- k_mean --------------------------------------
__global__ __launch_bounds__(256) void k_mean(const float* __restrict__ bimgs) {
    int idx = blockIdx.x * 256 + threadIdx.x;          // 0 .. 65535
    int b = idx >> 11, e = idx & 2047;
    const float* p = bimgs + (size_t)b * P_ * ENC_ + e;
    float s = 0.f;
#pragma unroll 4
    for (int pp = 0; pp < P_; ++pp) s += p[(size_t)pp * ENC_];
    g_mean[b * ENC_ + e] = s * (1.0f / 196.0f);
}

// ----------------------------- GEMM core -----------------------------------
// Shared inner machinery: block = 128 threads, C tile 32x64, micro 8x2/thread.
// Tiles live in caller-declared smem; MAIN loop body provided per mode below.

struct Tiles {
    float xs[32][68];
    float ws[64][68];
};

__device__ __forceinline__ void mma_tile(Tiles& s, u64 (&acc)[8][2], int tid) {
    int lane = tid & 31;
    int rb = (tid >> 5) * 8;
#pragma unroll 4
    for (int kq = 0; kq < 16; kq++) {
        ulonglong2 b0 = *(const ulonglong2*)&s.ws[lane][4 * kq];
        ulonglong2 b1 = *(const ulonglong2*)&s.ws[lane + 32][4 * kq];
#pragma unroll
        for (int i = 0; i < 8; i++) {
            ulonglong2 a = *(const ulonglong2*)&s.xs[rb + i][4 * kq];
            fma2(acc[i][0], a.x, b0.x);
            fma2(acc[i][0], a.y, b0.y);
            fma2(acc[i][1], a.x, b1.x);
            fma2(acc[i][1], a.y, b1.y);
        }
    }
}

// ----------------------------- mode 0: att1 --------------------------------
// att1[r0+32, j0+64] = bimgs rows . enc_att_W^T + bias   (K = ENC_)
__global__ __launch_bounds__(128, 4) void k_att1(
    const float* __restrict__ bimgs, const float* __restrict__ W0,
    const float* __restrict__ bias0)
{
    __shared__ __align__(16) Tiles s;
    int tid = threadIdx.x, lane = tid & 31;
    int j0 = blockIdx.x * 64, r0 = blockIdx.y * 32;
    u64 acc[8][2];
#pragma unroll
    for (int i = 0; i < 8; i++) { acc[i][0] = 0ull; acc[i][1] = 0ull; }

    for (int k0 = 0; k0 < ENC_; k0 += 64) {
#pragma unroll
        for (int i2 = 0; i2 < 4; i2++) {
            int ff = i2 * 128 + tid; int m = ff >> 4, q = ff & 15;
            *(float4*)&s.xs[m][q * 4] =
                *(const float4*)(bimgs + (size_t)(r0 + m) * ENC_ + k0 + q * 4);
        }
#pragma unroll
        for (int i2 = 0; i2 < 8; i2++) {
            int ff = i2 * 128 + tid; int c = ff >> 4, q = ff & 15;
            *(float4*)&s.ws[c][q * 4] =
                *(const float4*)(W0 + (size_t)(j0 + c) * ENC_ + k0 + q * 4);
        }
        __syncthreads();
        mma_tile(s, acc, tid);
        __syncthreads();
    }
    int rb = (tid >> 5) * 8;
#pragma unroll
    for (int i = 0; i < 8; i++)
#pragma unroll
        for (int jj = 0; jj < 2; jj++) {
            int jg = j0 + lane + 32 * jj;
            g_att1[(size_t)(r0 + rb + i) * ATT_ + jg] = fold2(acc[i][jj]) + bias0[jg];
        }
}

// ----------------------------- mode 1: init h0/c0 --------------------------
__global__ __launch_bounds__(128, 4) void k_init(
    const float* __restrict__ Wh, const float* __restrict__ Wc,
    const float* __restrict__ bh, const float* __restrict__ bc)
{
    __shared__ __align__(16) Tiles s;
    int tid = threadIdx.x, lane = tid & 31;
    int j0 = blockIdx.x * 64;
    u64 acc[8][2];
#pragma unroll
    for (int i = 0; i < 8; i++) { acc[i][0] = 0ull; acc[i][1] = 0ull; }

    for (int k0 = 0; k0 < ENC_; k0 += 64) {
#pragma unroll
        for (int i2 = 0; i2 < 4; i2++) {
            int ff = i2 * 128 + tid; int m = ff >> 4, q = ff & 15;
            *(float4*)&s.xs[m][q * 4] =
                *(const float4*)(g_mean + (size_t)m * ENC_ + k0 + q * 4);
        }
#pragma unroll
        for (int i2 = 0; i2 < 8; i2++) {
            int ff = i2 * 128 + tid; int c = ff >> 4, q = ff & 15;
            int jg = j0 + c;
            const float* src = (jg < DEC_) ? Wh + (size_t)jg * ENC_ + k0 + q * 4
                                           : Wc + (size_t)(jg - DEC_) * ENC_ + k0 + q * 4;
            *(float4*)&s.ws[c][q * 4] = *(const float4*)src;
        }
        __syncthreads();
        mma_tile(s, acc, tid);
        __syncthreads();
    }
    int rb = (tid >> 5) * 8;
#pragma unroll
    for (int i = 0; i < 8; i++)
#pragma unroll
        for (int jj = 0; jj < 2; jj++) {
            int jg = j0 + lane + 32 * jj;
            int row = rb + i;
            float v = fold2(acc[i][jj]);
            if (jg < DEC_) g_hbuf[0][row * DEC_ + jg] = v + bh[jg];
            else           g_cbuf[0][row * DEC_ + (jg - DEC_)] = v + bc[jg - DEC_];
        }
}

// ----------------------------- mode 2: LSTM gates partial ------------------
// blockIdx.y = K chunk (256 wide); X = gather [emb | xawe | h]; out partials.
__global__ __launch_bounds__(128, 4) void k_cell(
    const float* __restrict__ W_ih, const float* __restrict__ W_hh,
    const float* __restrict__ embW, const int* __restrict__ bx,
    int t, int par)
{
    __shared__ __align__(16) Tiles s;
    __shared__ int idx_s[32];
    int tid = threadIdx.x, lane = tid & 31;
    int j0 = blockIdx.x * 64;
    int kbeg = blockIdx.y * KCH_;
    if (tid < 32) idx_s[tid] = bx[tid * T_ + t];
    __syncthreads();
    u64 acc[8][2];
#pragma unroll
    for (int i = 0; i < 8; i++) { acc[i][0] = 0ull; acc[i][1] = 0ull; }

    for (int k0 = kbeg; k0 < kbeg + KCH_; k0 += 64) {
#pragma unroll
        for (int i2 = 0; i2 < 4; i2++) {
            int ff = i2 * 128 + tid; int m = ff >> 4, q = ff & 15;
            int kk = k0 + q * 4;
            const float* src;
            if (k0 < EMB_)             src = embW + (size_t)idx_s[m] * EMB_ + kk;
            else if (k0 < EMB_ + ENC_) src = g_xawe + m * ENC_ + (kk - EMB_);
            else                       src = g_hbuf[par] + m * DEC_ + (kk - (EMB_ + ENC_));
            *(float4*)&s.xs[m][q * 4] = *(const float4*)src;
        }
#pragma unroll
        for (int i2 = 0; i2 < 8; i2++) {
            int ff = i2 * 128 + tid; int c = ff >> 4, q = ff & 15;
            int kk = k0 + q * 4;
            int jg = j0 + c;
            const float* src = (k0 < EMB_ + ENC_)
                ? W_ih + (size_t)jg * (EMB_ + ENC_) + kk
                : W_hh + (size_t)jg * DEC_ + (kk - (EMB_ + ENC_));
            *(float4*)&s.ws[c][q * 4] = *(const float4*)src;
        }
        __syncthreads();
        mma_tile(s, acc, tid);
        __syncthreads();
    }
    int rb = (tid >> 5) * 8;
    float* dst = g_cpart + (size_t)blockIdx.y * B_ * 2048;
#pragma unroll
    for (int i = 0; i < 8; i++)
#pragma unroll
        for (int jj = 0; jj < 2; jj++)
            dst[(size_t)(rb + i) * 2048 + j0 + lane + 32 * jj] = fold2(acc[i][jj]);
}

// ----------------------------- mode 3: projections -------------------------
// segs: preds fc (PB blocks) / att2 (8) / gate (32).  K = DEC_.
__global__ __launch_bounds__(128, 4) void k_proj(
    const float* __restrict__ fc_W, const float* __restrict__ fc_b,
    const float* __restrict__ dec_att_W, const float* __restrict__ dec_att_b,
    const float* __restrict__ f_beta_W, const float* __restrict__ f_beta_b,
    const int* __restrict__ bxlen, float* __restrict__ out_pred,
    int t, int par, int pb)
{
    __shared__ __align__(16) Tiles s;
    int tid = threadIdx.x, lane = tid & 31;
    int cb = blockIdx.x;
    int seg, j0;
    const float* W; const float* X;
    if (cb < pb)           { seg = 0; j0 = cb * 64;            W = fc_W;      X = g_hnew; }
    else if (cb < pb + 8)  { seg = 1; j0 = (cb - pb) * 64;     W = dec_att_W; X = g_hbuf[par]; }
    else                   { seg = 2; j0 = (cb - pb - 8) * 64; W = f_beta_W;  X = g_hbuf[par]; }
    u64 acc[8][2];
#pragma unroll
    for (int i = 0; i < 8; i++) { acc[i][0] = 0ull; acc[i][1] = 0ull; }

    for (int k0 = 0; k0 < DEC_; k0 += 64) {
#pragma unroll
        for (int i2 = 0; i2 < 4; i2++) {
            int ff = i2 * 128 + tid; int m = ff >> 4, q = ff & 15;
            *(float4*)&s.xs[m][q * 4] =
                *(const float4*)(X + (size_t)m * DEC_ + k0 + q * 4);
        }
#pragma unroll
        for (int i2 = 0; i2 < 8; i2++) {
            int ff = i2 * 128 + tid; int c = ff >> 4, q = ff & 15;
            int jg = j0 + c;
            if (seg == 0 && jg >= V_) jg = V_ - 1;   // clamp load only
            *(float4*)&s.ws[c][q * 4] =
                *(const float4*)(W + (size_t)jg * DEC_ + k0 + q * 4);
        }
        __syncthreads();
        mma_tile(s, acc, tid);
        __syncthreads();
    }
    int rb = (tid >> 5) * 8;
#pragma unroll
    for (int i = 0; i < 8; i++) {
        int row = rb + i;
#pragma unroll
        for (int jj = 0; jj < 2; jj++) {
            int jg = j0 + lane + 32 * jj;
            float v = fold2(acc[i][jj]);
            if (seg == 0) {
                if (jg < V_) {
                    bool act = (t < bxlen[row]);
                    out_pred[((size_t)row * T_ + t) * V_ + jg] = act ? (v + fc_b[jg]) : 0.f;
                }
            } else if (seg == 1) {
                g_att2[row * ATT_ + jg] = v + dec_att_b[jg];
            } else {
                g_gate[row * ENC_ + jg] = sigf(v + f_beta_b[jg]);
            }
        }
    }
}

// ----------------------------- k_lstm --------------------------------------
__global__ __launch_bounds__(256) void k_lstm(
        const float* __restrict__ b_ih, const float* __restrict__ b_hh,
        const int* __restrict__ bxlen, int t, int par) {
    int idx = blockIdx.x * 256 + threadIdx.x;   // 0 .. 16383
    int m = idx >> 9, j = idx & 511;
    float s0 = b_ih[j] + b_hh[j];
    float s1 = b_ih[512 + j] + b_hh[512 + j];
    float s2 = b_ih[1024 + j] + b_hh[1024 + j];
    float s3 = b_ih[1536 + j] + b_hh[1536 + j];
#pragma unroll
    for (int kc = 0; kc < NCH_; kc++) {
        const float* p = g_cpart + ((size_t)kc * B_ + m) * 2048;
        s0 += p[j]; s1 += p[512 + j]; s2 += p[1024 + j]; s3 += p[1536 + j];
    }
    float i_ = sigf(s0), f_ = sigf(s1), g_ = tanhf(s2), o_ = sigf(s3);
    float h_old = g_hbuf[par][m * DEC_ + j];
    float c_old = g_cbuf[par][m * DEC_ + j];
    float cn = f_ * c_old + i_ * g_;
    float hn = o_ * tanhf(cn);
    g_hnew[m * DEC_ + j] = hn;
    bool act = (t < bxlen[m]);
    g_hbuf[par ^ 1][m * DEC_ + j] = act ? hn : h_old;
    g_cbuf[par ^ 1][m * DEC_ + j] = act ? cn : c_old;
}

// ----------------------------- k_escore ------------------------------------
__global__ __launch_bounds__(512) void k_escore(
        const float* __restrict__ full_att_W,
        const float* __restrict__ full_att_b,
        const int*   __restrict__ bxlen,
        float* __restrict__ out_alpha, int t) {
    __shared__ __align__(16) float att2_s[ATT_];
    __shared__ __align__(16) float w_s[ATT_];
    __shared__ float e_s[224];
    __shared__ float red[512];
    int b = blockIdx.x, tid = threadIdx.x;
    att2_s[tid] = g_att2[b * ATT_ + tid];
    w_s[tid] = full_att_W[tid];
    __syncthreads();
    int warp = tid >> 5, lane = tid & 31;
    float fb = full_att_b[0];
    for (int p = warp; p < P_; p += 16) {
        const float4* row = (const float4*)(g_att1 + ((size_t)b * P_ + p) * ATT_);
        float s = 0.f;
#pragma unroll
        for (int it = 0; it < 4; it++) {
            int k4 = lane + it * 32;
            float4 xv = row[k4];
            float4 av = *(const float4*)&att2_s[k4 * 4];
            float4 wv = *(const float4*)&w_s[k4 * 4];
            s = fmaf(fmaxf(xv.x + av.x, 0.f), wv.x, s);
            s = fmaf(fmaxf(xv.y + av.y, 0.f), wv.y, s);
            s = fmaf(fmaxf(xv.z + av.z, 0.f), wv.z, s);
            s = fmaf(fmaxf(xv.w + av.w, 0.f), wv.w, s);
        }
#pragma unroll
        for (int o = 16; o; o >>= 1) s += __shfl_xor_sync(0xffffffffu, s, o);
        if (!lane) e_s[p] = s + fb;
    }
    __syncthreads();
    float v = (tid < P_) ? e_s[tid] : -1e30f;
    red[tid] = v; __syncthreads();
    for (int o = 256; o; o >>= 1) { if (tid < o) red[tid] = fmaxf(red[tid], red[tid + o]); __syncthreads(); }
    float mx = red[0]; __syncthreads();
    float ex = (tid < P_) ? expf(v - mx) : 0.f;
    red[tid] = ex; __syncthreads();
    for (int o = 256; o; o >>= 1) { if (tid < o) red[tid] += red[tid + o]; __syncthreads(); }
    float inv = 1.0f / red[0];
    if (tid < P_) {
        float alpha = ex * inv;
        g_alpha[b * P_ + tid] = alpha;
        bool act = (t < bxlen[b]);
        out_alpha[((size_t)b * T_ + t) * P_ + tid] = act ? alpha : 0.f;
    }
}

// ----------------------------- k_awe ---------------------------------------
__global__ __launch_bounds__(256) void k_awe(const float* __restrict__ bimgs) {
    __shared__ float al[P_];
    int b = blockIdx.x, tid = threadIdx.x;
    if (tid < P_) al[tid] = g_alpha[b * P_ + tid];
    __syncthreads();
    int e = blockIdx.y * 256 + tid;
    const float* base = bimgs + (size_t)b * P_ * ENC_ + e;
    float s0 = 0.f, s1 = 0.f, s2 = 0.f, s3 = 0.f;
#pragma unroll 4
    for (int p = 0; p < P_; p += 4) {
        s0 = fmaf(al[p    ], base[(size_t)(p    ) * ENC_], s0);
        s1 = fmaf(al[p + 1], base[(size_t)(p + 1) * ENC_], s1);
        s2 = fmaf(al[p + 2], base[(size_t)(p + 2) * ENC_], s2);
        s3 = fmaf(al[p + 3], base[(size_t)(p + 3) * ENC_], s3);
    }
    g_xawe[b * ENC_ + e] = g_gate[b * ENC_ + e] * ((s0 + s1) + (s2 + s3));
}

// ----------------------------- launch --------------------------------------
extern "C" void kernel_launch(void* const* d_in, const int* in_sizes, int n_in,
                              void* d_out, int out_size) {
    (void)in_sizes; (void)n_in; (void)out_size;
    const float* bimgs      = (const float*)d_in[0];
    const int*   bx         = (const int*)  d_in[1];
    const int*   bxlen      = (const int*)  d_in[2];
    const float* emb_W      = (const float*)d_in[3];
    const float* enc_att_W  = (const float*)d_in[4];
    const float* enc_att_b  = (const float*)d_in[5];
    const float* dec_att_W  = (const float*)d_in[6];
    const float* dec_att_b  = (const float*)d_in[7];
    const float* full_att_W = (const float*)d_in[8];
    const float* full_att_b = (const float*)d_in[9];
    const float* init_h_W   = (const float*)d_in[10];
    const float* init_h_b   = (const float*)d_in[11];
    const float* init_c_W   = (const float*)d_in[12];
    const float* init_c_b   = (const float*)d_in[13];
    const float* f_beta_W   = (const float*)d_in[14];
    const float* f_beta_b   = (const float*)d_in[15];
    const float* W_ih       = (const float*)d_in[16];
    const float* b_ih       = (const float*)d_in[17];
    const float* W_hh       = (const float*)d_in[18];
    const float* b_hh       = (const float*)d_in[19];
    const float* fc_W       = (const float*)d_in[20];
    const float* fc_b       = (const float*)d_in[21];

    float* out_pred  = (float*)d_out;
    float* out_alpha = out_pred + (size_t)B_ * T_ * V_;

    k_mean<<<256, 256>>>(bimgs);
    k_att1<<<dim3(8, 196), 128>>>(bimgs, enc_att_W, enc_att_b);
    k_init<<<16, 128>>>(init_h_W, init_c_W, init_h_b, init_c_b);
    // initial att2 + gate from h0 (no preds segment: pb = 0)
    k_proj<<<40, 128>>>(fc_W, fc_b, dec_att_W, dec_att_b, f_beta_W, f_beta_b,
                        bxlen, out_pred, 0, 0, 0);

    for (int t = 0; t < T_; ++t) {
        int par = t & 1;
        k_escore<<<32, 512>>>(full_att_W, full_att_b, bxlen, out_alpha, t);
        k_awe<<<dim3(32, 8), 256>>>(bimgs);
        k_cell<<<dim3(32, NCH_), 128>>>(W_ih, W_hh, emb_W, bx, t, par);
        k_lstm<<<64, 256>>>(b_ih, b_hh, bxlen, t, par);
        // preds (157) + next att2 (8) + next gate (32)
        k_proj<<<197, 128>>>(fc_W, fc_b, dec_att_W, dec_att_b, f_beta_W, f_beta_b,
                             bxlen, out_pred, t, par ^ 1, 157);
    }
}

// round 7
// speedup vs baseline: 3.9535x; 1.5702x over previous
#include <cuda_runtime.h>
#include <math.h>

// ---------------------------------------------------------------------------
// AttentionLSTM forward, B=32 T=128 P=196 ENC=2048 DEC=ATT=EMB=512 V=10000.
// fp32 with packed fma.rn.f32x2.  GEMM engine: 128 thr, C tile 32x64,
// micro 8x2/thread, BK=32, cp.async double-buffered smem tiles.
// ---------------------------------------------------------------------------

#define B_   32
#define T_   128
#define P_   196
#define ENC_ 2048
#define DEC_ 512
#define ATT_ 512
#define EMB_ 512
#define V_   10000
#define XK_  3072
#define NCH_ 12
#define KCH_ (XK_ / NCH_)     // 256
#define BK_  32

typedef unsigned long long u64;

__device__ __forceinline__ void fma2(u64& c, u64 a, u64 b) {
    asm("fma.rn.f32x2 %0, %1, %2, %0;" : "+l"(c) : "l"(a), "l"(b));
}
__device__ __forceinline__ float fold2(u64 v) {
    return __uint_as_float((unsigned)v) + __uint_as_float((unsigned)(v >> 32));
}
__device__ __forceinline__ float sigf(float x) { return 1.0f / (1.0f + expf(-x)); }

__device__ __forceinline__ unsigned sm32(const void* p) {
    return (unsigned)__cvta_generic_to_shared(p);
}
__device__ __forceinline__ void cpa16(unsigned dst, const float* src) {
    asm volatile("cp.async.cg.shared.global [%0], [%1], 16;" :: "r"(dst), "l"(src));
}
#define CP_COMMIT() asm volatile("cp.async.commit_group;")
#define CP_WAIT1()  asm volatile("cp.async.wait_group 1;")
#define CP_WAIT0()  asm volatile("cp.async.wait_group 0;")

// ----------------------------- device scratch ------------------------------
__device__ float g_att1[B_ * P_ * ATT_];         // 12.8 MB
__device__ float g_mean[B_ * ENC_];
__device__ float g_hbuf[2][B_ * DEC_];
__device__ float g_cbuf[2][B_ * DEC_];
__device__ float g_hnew[B_ * DEC_];
__device__ float g_att2[B_ * ATT_];
__device__ float g_gate[B_ * ENC_];
__device__ float g_xawe[B_ * ENC_];
__device__ float g_alpha[B_ * P_];
__device__ float g_cpart[NCH_ * B_ * 2048];      // 3 MB LSTM gate partials

// ----------------------------- GEMM core -----------------------------------
// 32 rows x 64 cols x BK=32; stride 36 floats (36 mod 32 == 4 -> LDS.128
// conflict-free for the strided ws reads; xs reads are broadcasts).
struct Tiles {
    float xs[32][36];
    float ws[64][36];
};

__device__ __forceinline__ void mma_tile(const Tiles& s, u64 (&acc)[8][2], int tid) {
    int lane = tid & 31;
    int rb = (tid >> 5) * 8;
#pragma unroll
    for (int kq = 0; kq < 8; kq++) {
        ulonglong2 b0 = *(const ulonglong2*)&s.ws[lane][4 * kq];
        ulonglong2 b1 = *(const ulonglong2*)&s.ws[lane + 32][4 * kq];
#pragma unroll
        for (int i = 0; i < 8; i++) {
            ulonglong2 a = *(const ulonglong2*)&s.xs[rb + i][4 * kq];
            fma2(acc[i][0], a.x, b0.x);
            fma2(acc[i][0], a.y, b0.y);
            fma2(acc[i][1], a.x, b1.x);
            fma2(acc[i][1], a.y, b1.y);
        }
    }
}

// ----------------------------- k_mean --------------------------------------
__global__ __launch_bounds__(256) void k_mean(const float* __restrict__ bimgs) {
    int idx = blockIdx.x * 256 + threadIdx.x;          // 0 .. 65535
    int b = idx >> 11, e = idx & 2047;
    const float* p = bimgs + (size_t)b * P_ * ENC_ + e;
    float s = 0.f;
#pragma unroll 4
    for (int pp = 0; pp < P_; ++pp) s += p[(size_t)pp * ENC_];
    g_mean[b * ENC_ + e] = s * (1.0f / 196.0f);
}

// ----------------------------- k_att1 --------------------------------------
__global__ __launch_bounds__(128, 4) void k_att1(
    const float* __restrict__ bimgs, const float* __restrict__ W0,
    const float* __restrict__ bias0)
{
    __shared__ __align__(16) Tiles tb[2];
    int tid = threadIdx.x, lane = tid & 31;
    int j0 = blockIdx.x * 64, r0 = blockIdx.y * 32;
    u64 acc[8][2];
#pragma unroll
    for (int i = 0; i < 8; i++) { acc[i][0] = 0ull; acc[i][1] = 0ull; }

    auto load = [&](int s, int k0) {
#pragma unroll
        for (int i2 = 0; i2 < 2; i2++) {
            int ff = i2 * 128 + tid, m = ff >> 3, q = ff & 7;
            cpa16(sm32(&tb[s].xs[m][q * 4]),
                  bimgs + (size_t)(r0 + m) * ENC_ + k0 + q * 4);
        }
#pragma unroll
        for (int i2 = 0; i2 < 4; i2++) {
            int ff = i2 * 128 + tid, c = ff >> 3, q = ff & 7;
            cpa16(sm32(&tb[s].ws[c][q * 4]),
                  W0 + (size_t)(j0 + c) * ENC_ + k0 + q * 4);
        }
        CP_COMMIT();
    };

    const int NIT = ENC_ / BK_;
    load(0, 0);
    for (int it = 0; it < NIT; ++it) {
        if (it + 1 < NIT) { load((it + 1) & 1, (it + 1) * BK_); CP_WAIT1(); }
        else              { CP_WAIT0(); }
        __syncthreads();
        mma_tile(tb[it & 1], acc, tid);
        __syncthreads();
    }
    int rb = (tid >> 5) * 8;
#pragma unroll
    for (int i = 0; i < 8; i++)
#pragma unroll
        for (int jj = 0; jj < 2; jj++) {
            int jg = j0 + lane + 32 * jj;
            g_att1[(size_t)(r0 + rb + i) * ATT_ + jg] = fold2(acc[i][jj]) + bias0[jg];
        }
}

// ----------------------------- k_init --------------------------------------
__global__ __launch_bounds__(128, 4) void k_init(
    const float* __restrict__ Wh, const float* __restrict__ Wc,
    const float* __restrict__ bh, const float* __restrict__ bc)
{
    __shared__ __align__(16) Tiles tb[2];
    int tid = threadIdx.x, lane = tid & 31;
    int j0 = blockIdx.x * 64;
    u64 acc[8][2];
#pragma unroll
    for (int i = 0; i < 8; i++) { acc[i][0] = 0ull; acc[i][1] = 0ull; }

    auto load = [&](int s, int k0) {
#pragma unroll
        for (int i2 = 0; i2 < 2; i2++) {
            int ff = i2 * 128 + tid, m = ff >> 3, q = ff & 7;
            cpa16(sm32(&tb[s].xs[m][q * 4]), g_mean + (size_t)m * ENC_ + k0 + q * 4);
        }
#pragma unroll
        for (int i2 = 0; i2 < 4; i2++) {
            int ff = i2 * 128 + tid, c = ff >> 3, q = ff & 7;
            int jg = j0 + c;
            const float* src = (jg < DEC_) ? Wh + (size_t)jg * ENC_ + k0 + q * 4
                                           : Wc + (size_t)(jg - DEC_) * ENC_ + k0 + q * 4;
            cpa16(sm32(&tb[s].ws[c][q * 4]), src);
        }
        CP_COMMIT();
    };

    const int NIT = ENC_ / BK_;
    load(0, 0);
    for (int it = 0; it < NIT; ++it) {
        if (it + 1 < NIT) { load((it + 1) & 1, (it + 1) * BK_); CP_WAIT1(); }
        else              { CP_WAIT0(); }
        __syncthreads();
        mma_tile(tb[it & 1], acc, tid);
        __syncthreads();
    }
    int rb = (tid >> 5) * 8;
#pragma unroll
    for (int i = 0; i < 8; i++)
#pragma unroll
        for (int jj = 0; jj < 2; jj++) {
            int jg = j0 + lane + 32 * jj;
            int row = rb + i;
            float v = fold2(acc[i][jj]);
            if (jg < DEC_) g_hbuf[0][row * DEC_ + jg] = v + bh[jg];
            else           g_cbuf[0][row * DEC_ + (jg - DEC_)] = v + bc[jg - DEC_];
        }
}

// ----------------------------- k_cell --------------------------------------
// blockIdx.y = K chunk (256 wide); X = gather [emb | xawe | h]; out partials.
__global__ __launch_bounds__(128, 4) void k_cell(
    const float* __restrict__ W_ih, const float* __restrict__ W_hh,
    const float* __restrict__ embW, const int* __restrict__ bx,
    int t, int par)
{
    __shared__ __align__(16) Tiles tb[2];
    __shared__ int idx_s[32];
    int tid = threadIdx.x, lane = tid & 31;
    int j0 = blockIdx.x * 64;
    int kbeg = blockIdx.y * KCH_;
    if (tid < 32) idx_s[tid] = bx[tid * T_ + t];
    __syncthreads();
    u64 acc[8][2];
#pragma unroll
    for (int i = 0; i < 8; i++) { acc[i][0] = 0ull; acc[i][1] = 0ull; }

    auto load = [&](int s, int k0) {
#pragma unroll
        for (int i2 = 0; i2 < 2; i2++) {
            int ff = i2 * 128 + tid, m = ff >> 3, q = ff & 7;
            int kk = k0 + q * 4;
            const float* src;
            if (k0 < EMB_)             src = embW + (size_t)idx_s[m] * EMB_ + kk;
            else if (k0 < EMB_ + ENC_) src = g_xawe + m * ENC_ + (kk - EMB_);
            else                       src = g_hbuf[par] + m * DEC_ + (kk - (EMB_ + ENC_));
            cpa16(sm32(&tb[s].xs[m][q * 4]), src);
        }
#pragma unroll
        for (int i2 = 0; i2 < 4; i2++) {
            int ff = i2 * 128 + tid, c = ff >> 3, q = ff & 7;
            int kk = k0 + q * 4;
            int jg = j0 + c;
            const float* src = (k0 < EMB_ + ENC_)
                ? W_ih + (size_t)jg * (EMB_ + ENC_) + kk
                : W_hh + (size_t)jg * DEC_ + (kk - (EMB_ + ENC_));
            cpa16(sm32(&tb[s].ws[c][q * 4]), src);
        }
        CP_COMMIT();
    };

    const int NIT = KCH_ / BK_;
    load(0, kbeg);
    for (int it = 0; it < NIT; ++it) {
        if (it + 1 < NIT) { load((it + 1) & 1, kbeg + (it + 1) * BK_); CP_WAIT1(); }
        else              { CP_WAIT0(); }
        __syncthreads();
        mma_tile(tb[it & 1], acc, tid);
        __syncthreads();
    }
    int rb = (tid >> 5) * 8;
    float* dst = g_cpart + (size_t)blockIdx.y * B_ * 2048;
#pragma unroll
    for (int i = 0; i < 8; i++)
#pragma unroll
        for (int jj = 0; jj < 2; jj++)
            dst[(size_t)(rb + i) * 2048 + j0 + lane + 32 * jj] = fold2(acc[i][jj]);
}

// ----------------------------- k_proj --------------------------------------
// segs: preds fc (pb blocks) / att2 (8) / gate (32).  K = DEC_.
__global__ __launch_bounds__(128, 4) void k_proj(
    const float* __restrict__ fc_W, const float* __restrict__ fc_b,
    const float* __restrict__ dec_att_W, const float* __restrict__ dec_att_b,
    const float* __restrict__ f_beta_W, const float* __restrict__ f_beta_b,
    const int* __restrict__ bxlen, float* __restrict__ out_pred,
    int t, int par, int pb)
{
    __shared__ __align__(16) Tiles tb[2];
    int tid = threadIdx.x, lane = tid & 31;
    int cb = blockIdx.x;
    int seg, j0;
    const float* W; const float* X;
    if (cb < pb)           { seg = 0; j0 = cb * 64;            W = fc_W;      X = g_hnew; }
    else if (cb < pb + 8)  { seg = 1; j0 = (cb - pb) * 64;     W = dec_att_W; X = g_hbuf[par]; }
    else                   { seg = 2; j0 = (cb - pb - 8) * 64; W = f_beta_W;  X = g_hbuf[par]; }
    u64 acc[8][2];
#pragma unroll
    for (int i = 0; i < 8; i++) { acc[i][0] = 0ull; acc[i][1] = 0ull; }

    auto load = [&](int s, int k0) {
#pragma unroll
        for (int i2 = 0; i2 < 2; i2++) {
            int ff = i2 * 128 + tid, m = ff >> 3, q = ff & 7;
            cpa16(sm32(&tb[s].xs[m][q * 4]), X + (size_t)m * DEC_ + k0 + q * 4);
        }
#pragma unroll
        for (int i2 = 0; i2 < 4; i2++) {
            int ff = i2 * 128 + tid, c = ff >> 3, q = ff & 7;
            int jg = j0 + c;
            if (seg == 0 && jg >= V_) jg = V_ - 1;   // clamp load only
            cpa16(sm32(&tb[s].ws[c][q * 4]), W + (size_t)jg * DEC_ + k0 + q * 4);
        }
        CP_COMMIT();
    };

    const int NIT = DEC_ / BK_;
    load(0, 0);
    for (int it = 0; it < NIT; ++it) {
        if (it + 1 < NIT) { load((it + 1) & 1, (it + 1) * BK_); CP_WAIT1(); }
        else              { CP_WAIT0(); }
        __syncthreads();
        mma_tile(tb[it & 1], acc, tid);
        __syncthreads();
    }
    int rb = (tid >> 5) * 8;
#pragma unroll
    for (int i = 0; i < 8; i++) {
        int row = rb + i;
#pragma unroll
        for (int jj = 0; jj < 2; jj++) {
            int jg = j0 + lane + 32 * jj;
            float v = fold2(acc[i][jj]);
            if (seg == 0) {
                if (jg < V_) {
                    bool act = (t < bxlen[row]);
                    out_pred[((size_t)row * T_ + t) * V_ + jg] = act ? (v + fc_b[jg]) : 0.f;
                }
            } else if (seg == 1) {
                g_att2[row * ATT_ + jg] = v + dec_att_b[jg];
            } else {
                g_gate[row * ENC_ + jg] = sigf(v + f_beta_b[jg]);
            }
        }
    }
}

// ----------------------------- k_lstm --------------------------------------
__global__ __launch_bounds__(256) void k_lstm(
        const float* __restrict__ b_ih, const float* __restrict__ b_hh,
        const int* __restrict__ bxlen, int t, int par) {
    int idx = blockIdx.x * 256 + threadIdx.x;   // 0 .. 16383
    int m = idx >> 9, j = idx & 511;
    float s0 = b_ih[j] + b_hh[j];
    float s1 = b_ih[512 + j] + b_hh[512 + j];
    float s2 = b_ih[1024 + j] + b_hh[1024 + j];
    float s3 = b_ih[1536 + j] + b_hh[1536 + j];
#pragma unroll
    for (int kc = 0; kc < NCH_; kc++) {
        const float* p = g_cpart + ((size_t)kc * B_ + m) * 2048;
        s0 += p[j]; s1 += p[512 + j]; s2 += p[1024 + j]; s3 += p[1536 + j];
    }
    float i_ = sigf(s0), f_ = sigf(s1), g_ = tanhf(s2), o_ = sigf(s3);
    float h_old = g_hbuf[par][m * DEC_ + j];
    float c_old = g_cbuf[par][m * DEC_ + j];
    float cn = f_ * c_old + i_ * g_;
    float hn = o_ * tanhf(cn);
    g_hnew[m * DEC_ + j] = hn;
    bool act = (t < bxlen[m]);
    g_hbuf[par ^ 1][m * DEC_ + j] = act ? hn : h_old;
    g_cbuf[par ^ 1][m * DEC_ + j] = act ? cn : c_old;
}

// ----------------------------- k_escore ------------------------------------
__global__ __launch_bounds__(512) void k_escore(
        const float* __restrict__ full_att_W,
        const float* __restrict__ full_att_b,
        const int*   __restrict__ bxlen,
        float* __restrict__ out_alpha, int t) {
    __shared__ __align__(16) float att2_s[ATT_];
    __shared__ __align__(16) float w_s[ATT_];
    __shared__ float e_s[224];
    __shared__ float red[512];
    int b = blockIdx.x, tid = threadIdx.x;
    att2_s[tid] = g_att2[b * ATT_ + tid];
    w_s[tid] = full_att_W[tid];
    __syncthreads();
    int warp = tid >> 5, lane = tid & 31;
    float fb = full_att_b[0];
    for (int p = warp; p < P_; p += 16) {
        const float4* row = (const float4*)(g_att1 + ((size_t)b * P_ + p) * ATT_);
        float s = 0.f;
#pragma unroll
        for (int it = 0; it < 4; it++) {
            int k4 = lane + it * 32;
            float4 xv = row[k4];
            float4 av = *(const float4*)&att2_s[k4 * 4];
            float4 wv = *(const float4*)&w_s[k4 * 4];
            s = fmaf(fmaxf(xv.x + av.x, 0.f), wv.x, s);
            s = fmaf(fmaxf(xv.y + av.y, 0.f), wv.y, s);
            s = fmaf(fmaxf(xv.z + av.z, 0.f), wv.z, s);
            s = fmaf(fmaxf(xv.w + av.w, 0.f), wv.w, s);
        }
#pragma unroll
        for (int o = 16; o; o >>= 1) s += __shfl_xor_sync(0xffffffffu, s, o);
        if (!lane) e_s[p] = s + fb;
    }
    __syncthreads();
    float v = (tid < P_) ? e_s[tid] : -1e30f;
    red[tid] = v; __syncthreads();
    for (int o = 256; o; o >>= 1) { if (tid < o) red[tid] = fmaxf(red[tid], red[tid + o]); __syncthreads(); }
    float mx = red[0]; __syncthreads();
    float ex = (tid < P_) ? expf(v - mx) : 0.f;
    red[tid] = ex; __syncthreads();
    for (int o = 256; o; o >>= 1) { if (tid < o) red[tid] += red[tid + o]; __syncthreads(); }
    float inv = 1.0f / red[0];
    if (tid < P_) {
        float alpha = ex * inv;
        g_alpha[b * P_ + tid] = alpha;
        bool act = (t < bxlen[b]);
        out_alpha[((size_t)b * T_ + t) * P_ + tid] = act ? alpha : 0.f;
    }
}

// ----------------------------- k_awe ---------------------------------------
__global__ __launch_bounds__(256) void k_awe(const float* __restrict__ bimgs) {
    __shared__ float al[P_];
    int b = blockIdx.x, tid = threadIdx.x;
    if (tid < P_) al[tid] = g_alpha[b * P_ + tid];
    __syncthreads();
    int e = blockIdx.y * 256 + tid;
    const float* base = bimgs + (size_t)b * P_ * ENC_ + e;
    float s0 = 0.f, s1 = 0.f, s2 = 0.f, s3 = 0.f;
#pragma unroll 4
    for (int p = 0; p < P_; p += 4) {
        s0 = fmaf(al[p    ], base[(size_t)(p    ) * ENC_], s0);
        s1 = fmaf(al[p + 1], base[(size_t)(p + 1) * ENC_], s1);
        s2 = fmaf(al[p + 2], base[(size_t)(p + 2) * ENC_], s2);
        s3 = fmaf(al[p + 3], base[(size_t)(p + 3) * ENC_], s3);
    }
    g_xawe[b * ENC_ + e] = g_gate[b * ENC_ + e] * ((s0 + s1) + (s2 + s3));
}

// ----------------------------- launch --------------------------------------
extern "C" void kernel_launch(void* const* d_in, const int* in_sizes, int n_in,
                              void* d_out, int out_size) {
    (void)in_sizes; (void)n_in; (void)out_size;
    const float* bimgs      = (const float*)d_in[0];
    const int*   bx         = (const int*)  d_in[1];
    const int*   bxlen      = (const int*)  d_in[2];
    const float* emb_W      = (const float*)d_in[3];
    const float* enc_att_W  = (const float*)d_in[4];
    const float* enc_att_b  = (const float*)d_in[5];
    const float* dec_att_W  = (const float*)d_in[6];
    const float* dec_att_b  = (const float*)d_in[7];
    const float* full_att_W = (const float*)d_in[8];
    const float* full_att_b = (const float*)d_in[9];
    const float* init_h_W   = (const float*)d_in[10];
    const float* init_h_b   = (const float*)d_in[11];
    const float* init_c_W   = (const float*)d_in[12];
    const float* init_c_b   = (const float*)d_in[13];
    const float* f_beta_W   = (const float*)d_in[14];
    const float* f_beta_b   = (const float*)d_in[15];
    const float* W_ih       = (const float*)d_in[16];
    const float* b_ih       = (const float*)d_in[17];
    const float* W_hh       = (const float*)d_in[18];
    const float* b_hh       = (const float*)d_in[19];
    const float* fc_W       = (const float*)d_in[20];
    const float* fc_b       = (const float*)d_in[21];

    float* out_pred  = (float*)d_out;
    float* out_alpha = out_pred + (size_t)B_ * T_ * V_;

    k_mean<<<256, 256>>>(bimgs);
    k_att1<<<dim3(8, 196), 128>>>(bimgs, enc_att_W, enc_att_b);
    k_init<<<16, 128>>>(init_h_W, init_c_W, init_h_b, init_c_b);
    // initial att2 + gate from h0 (no preds segment: pb = 0)
    k_proj<<<40, 128>>>(fc_W, fc_b, dec_att_W, dec_att_b, f_beta_W, f_beta_b,
                        bxlen, out_pred, 0, 0, 0);

    for (int t = 0; t < T_; ++t) {
        int par = t & 1;
        k_escore<<<32, 512>>>(full_att_W, full_att_b, bxlen, out_alpha, t);
        k_awe<<<dim3(32, 8), 256>>>(bimgs);
        k_cell<<<dim3(32, NCH_), 128>>>(W_ih, W_hh, emb_W, bx, t, par);
        k_lstm<<<64, 256>>>(b_ih, b_hh, bxlen, t, par);
        // preds (157) + next att2 (8) + next gate (32)
        k_proj<<<197, 128>>>(fc_W, fc_b, dec_att_W, dec_att_b, f_beta_W, f_beta_b,
                             bxlen, out_pred, t, par ^ 1, 157);
    }
}